// round 9
// baseline (speedup 1.0000x reference)
#include <cuda_runtime.h>
#include <math.h>

// RoIPooling: feat [B,C,50,50] f32, rois [N,5] f32, img scalars -> out [N,C,7,7] f32.
// Bench: B=2, C=256, N=128, IMG=800.
//
// K1: feat[b][c][p] -> g_featT[b][p][c]; 4 tiles per block (MLP=4 per thread).
// K2: block = (roi, channel-half); warp = bin (warp-uniform bounds, no divergence);
//     lane = 4 channels (float4, fully coalesced). smem-staged direct write to out.

#define C_DIM 256
#define FH 50
#define FW 50
#define NPIX (FH * FW)
#define OH 7
#define OW 7
#define QD (OH * OW)
#define MAX_B 4

__device__ __align__(16) float g_featT[MAX_B * NPIX * C_DIM];   // [b][p][c]

__device__ __forceinline__ float decode_dim(const void* p) {
    int v = *reinterpret_cast<const int*>(p);
    if (v > 0 && v < 1000000) return (float)v;   // int scalar (800 = 0x320)
    return __int_as_float(v);                     // float bits
}

__device__ __forceinline__ float4 f4max(float4 a, float4 b) {
    return make_float4(fmaxf(a.x, b.x), fmaxf(a.y, b.y),
                       fmaxf(a.z, b.z), fmaxf(a.w, b.w));
}

// ---- K1: transpose, 4 tiles per 256-thread block, float4 both sides ----
#define PXT ((NPIX + 31) / 32)     // 79 pixel tiles
#define CT  (C_DIM / 32)           // 8 channel tiles

__global__ void __launch_bounds__(256)
transpose_in(const float* __restrict__ feat, int ntiles) {
    __shared__ float s[4][32][33];
    int tid = threadIdx.x;
    int t0 = blockIdx.x * 4;

    int cl = tid >> 3;
    int pq = (tid & 7) << 2;

    // 4 independent loads first (MLP = 4)
    #pragma unroll
    for (int k = 0; k < 4; ++k) {
        int t = t0 + k;
        if (t < ntiles) {
            int pt = t % PXT;
            int ct = (t / PXT) % CT;
            int b  = t / (PXT * CT);
            int p = pt * 32 + pq;
            if (p < NPIX) {          // p%4==0, NPIX%4==0 -> p+3 < NPIX
                float4 v = *reinterpret_cast<const float4*>(
                    feat + ((size_t)(b * C_DIM + ct * 32 + cl)) * NPIX + p);
                s[k][cl][pq + 0] = v.x;
                s[k][cl][pq + 1] = v.y;
                s[k][cl][pq + 2] = v.z;
                s[k][cl][pq + 3] = v.w;
            }
        }
    }
    __syncthreads();

    int pl = tid >> 3;
    int cq = (tid & 7) << 2;
    #pragma unroll
    for (int k = 0; k < 4; ++k) {
        int t = t0 + k;
        if (t < ntiles) {
            int pt = t % PXT;
            int ct = (t / PXT) % CT;
            int b  = t / (PXT * CT);
            int p = pt * 32 + pl;
            if (p < NPIX) {
                float4 v;
                v.x = s[k][cq + 0][pl];
                v.y = s[k][cq + 1][pl];
                v.z = s[k][cq + 2][pl];
                v.w = s[k][cq + 3][pl];
                *reinterpret_cast<float4*>(
                    g_featT + ((size_t)b * NPIX + p) * C_DIM + ct * 32 + cq) = v;
            }
        }
    }
}

// ---- K2: block = (roi, c-half); warp = bin; lane = 4 channels ----
__global__ void __launch_bounds__(256)
roipool_pool(const float* __restrict__ rois,
             const void* __restrict__ img_h_p,
             const void* __restrict__ img_w_p,
             float* __restrict__ out) {
    __shared__ __align__(16) float s[128 * QD];   // [c_local][q], stride QD=49
    int n    = blockIdx.x >> 1;
    int half = blockIdx.x & 1;
    int w    = threadIdx.x >> 5;                  // warp 0..7
    int lane = threadIdx.x & 31;

    // ---- roi-level math (block-uniform, exact reference rounding) ----
    float img_h = decode_dim(img_h_p);
    float img_w = decode_dim(img_w_p);
    float sh = __fdiv_rn((float)FH, img_h);
    float sw = __fdiv_rn((float)FW, img_w);

    const float* r = rois + n * 5;
    int bidx = (int)r[0];
    int x1 = max((int)floorf(__fmul_rn(r[1], sw)), 0);
    int y1 = max((int)floorf(__fmul_rn(r[2], sh)), 0);
    int x2 = min((int)floorf(__fmul_rn(r[3], sw)), FW);
    int y2 = min((int)floorf(__fmul_rn(r[4], sh)), FH);

    float bh = __fdiv_rn((float)max(y2 - y1, 1), (float)OH);
    float bw = __fdiv_rn((float)max(x2 - x1, 1), (float)OW);
    float y1f = (float)y1, x1f = (float)x1;

    const float* base = g_featT + (size_t)bidx * (NPIX * C_DIM)
                                + half * 128 + lane * 4;

    // ---- warp per bin: q = w, w+8, ... (all bounds warp-uniform) ----
    for (int q = w; q < QD; q += 8) {
        int oh = q / OW;
        int ow = q % OW;
        // mul then add, each correctly rounded (no FMA contraction) — matches jnp
        int ys = (int)floorf(__fadd_rn(y1f, __fmul_rn((float)oh,       bh)));
        int ye = (int)floorf(__fadd_rn(y1f, __fmul_rn((float)(oh + 1), bh)));
        int xs = (int)floorf(__fadd_rn(x1f, __fmul_rn((float)ow,       bw)));
        int xe = (int)floorf(__fadd_rn(x1f, __fmul_rn((float)(ow + 1), bw)));
        ys = min(max(ys, 0), FH - 1);
        ye = min(max(ye, 0), FH);
        xs = min(max(xs, 0), FW - 1);
        xe = min(max(xe, 0), FW);

        int rows = ye - ys;
        int cols = xe - xs;
        bool valid = (rows > 0) && (cols > 0);

        float4 m0 = make_float4(-INFINITY, -INFINITY, -INFINITY, -INFINITY);
        float4 m1 = m0;
        const float* bp = base + (size_t)(ys * FW + xs) * C_DIM;
        for (int y = 0; y < rows; ++y) {
            const float* rp = bp + (size_t)y * (FW * C_DIM);
            int x = 0;
            for (; x + 2 <= cols; x += 2) {
                float4 a = *reinterpret_cast<const float4*>(rp + (size_t)x * C_DIM);
                float4 b = *reinterpret_cast<const float4*>(rp + (size_t)(x + 1) * C_DIM);
                m0 = f4max(m0, a);
                m1 = f4max(m1, b);
            }
            if (x < cols)
                m0 = f4max(m0, *reinterpret_cast<const float4*>(rp + (size_t)x * C_DIM));
        }
        float4 m = f4max(m0, m1);
        if (!valid) m = make_float4(0.f, 0.f, 0.f, 0.f);

        int cb = lane * 4;
        s[(cb + 0) * QD + q] = m.x;
        s[(cb + 1) * QD + q] = m.y;
        s[(cb + 2) * QD + q] = m.z;
        s[(cb + 3) * QD + q] = m.w;
    }
    __syncthreads();

    // ---- drain: 128*49 floats contiguous in out[n][half*128..][q] ----
    float4* dst = reinterpret_cast<float4*>(
        out + (size_t)n * (C_DIM * QD) + (size_t)half * 128 * QD);
    const float4* ss = reinterpret_cast<const float4*>(s);
    #pragma unroll
    for (int i = 0; i < (128 * QD) / 4 / 256 + 1; ++i) {
        int idx = threadIdx.x + i * 256;
        if (idx < (128 * QD) / 4)
            dst[idx] = ss[idx];
    }
}

extern "C" void kernel_launch(void* const* d_in, const int* in_sizes, int n_in,
                              void* d_out, int out_size) {
    const float* feat = (const float*)d_in[0];
    const float* rois = (const float*)d_in[1];
    const void*  imh  = d_in[2];
    const void*  imw  = d_in[3];
    float* out = (float*)d_out;

    int B = in_sizes[0] / (C_DIM * NPIX);
    int nrois = in_sizes[1] / 5;

    int ntiles = PXT * CT * B;                   // 1264 for B=2
    transpose_in<<<(ntiles + 3) / 4, 256>>>(feat, ntiles);

    roipool_pool<<<nrois * 2, 256>>>(rois, imh, imw, out);
}

// round 10
// speedup vs baseline: 1.9346x; 1.9346x over previous
#include <cuda_runtime.h>
#include <math.h>

// RoIPooling: feat [B,C,50,50] f32, rois [N,5] f32, img scalars -> out [N,C,7,7] f32.
// Bench: B=2, C=256, N=128, IMG=800.
//
// R6 structure (best measured), with the ILP-4 transpose from R9-K1:
//  1) transpose_in : 4 tiles per 256-thread block (MLP=4), float4 both sides.
//  2) roipool_main : block per bin (6272 x 64 thr); thread = 4 channels (float4);
//                    block-uniform smem offset table -> flat unrolled loads.
//  3) transpose_out: g_outT[n][q][c] -> out[n][c][q]; coalesced, float4 drain.

#define C_DIM 256
#define FH 50
#define FW 50
#define NPIX (FH * FW)
#define OH 7
#define OW 7
#define QD (OH * OW)
#define MAX_B 4
#define MAX_ROIS 512
#define MAX_CNT 96

__device__ __align__(16) float g_featT[MAX_B * NPIX * C_DIM];   // [b][p][c]
__device__ __align__(16) float g_outT[MAX_ROIS * QD * C_DIM];   // [bin][c]

__device__ __forceinline__ float decode_dim(const void* p) {
    int v = *reinterpret_cast<const int*>(p);
    if (v > 0 && v < 1000000) return (float)v;   // int scalar (800 = 0x320)
    return __int_as_float(v);                     // float bits
}

__device__ __forceinline__ float4 f4max(float4 a, float4 b) {
    return make_float4(fmaxf(a.x, b.x), fmaxf(a.y, b.y),
                       fmaxf(a.z, b.z), fmaxf(a.w, b.w));
}

// ---- K1: transpose, 4 tiles per 256-thread block, float4 both sides ----
#define PXT ((NPIX + 31) / 32)     // 79 pixel tiles
#define CT  (C_DIM / 32)           // 8 channel tiles

__global__ void __launch_bounds__(256)
transpose_in(const float* __restrict__ feat, int ntiles) {
    __shared__ float s[4][32][33];
    int tid = threadIdx.x;
    int t0 = blockIdx.x * 4;

    int cl = tid >> 3;
    int pq = (tid & 7) << 2;

    // 4 independent loads issued back-to-back (MLP = 4)
    #pragma unroll
    for (int k = 0; k < 4; ++k) {
        int t = t0 + k;
        if (t < ntiles) {
            int pt = t % PXT;
            int ct = (t / PXT) % CT;
            int b  = t / (PXT * CT);
            int p = pt * 32 + pq;
            if (p < NPIX) {          // p%4==0, NPIX%4==0 -> p+3 < NPIX
                float4 v = *reinterpret_cast<const float4*>(
                    feat + ((size_t)(b * C_DIM + ct * 32 + cl)) * NPIX + p);
                s[k][cl][pq + 0] = v.x;
                s[k][cl][pq + 1] = v.y;
                s[k][cl][pq + 2] = v.z;
                s[k][cl][pq + 3] = v.w;
            }
        }
    }
    __syncthreads();

    int pl = tid >> 3;
    int cq = (tid & 7) << 2;
    #pragma unroll
    for (int k = 0; k < 4; ++k) {
        int t = t0 + k;
        if (t < ntiles) {
            int pt = t % PXT;
            int ct = (t / PXT) % CT;
            int b  = t / (PXT * CT);
            int p = pt * 32 + pl;
            if (p < NPIX) {
                float4 v;
                v.x = s[k][cq + 0][pl];
                v.y = s[k][cq + 1][pl];
                v.z = s[k][cq + 2][pl];
                v.w = s[k][cq + 3][pl];
                *reinterpret_cast<float4*>(
                    g_featT + ((size_t)b * NPIX + p) * C_DIM + ct * 32 + cq) = v;
            }
        }
    }
}

// ---- K2: block per bin; 64 threads; thread = 4 channels (float4) ----
__global__ void __launch_bounds__(64)
roipool_main(const float* __restrict__ rois,
             const void* __restrict__ img_h_p,
             const void* __restrict__ img_w_p) {
    int bin = blockIdx.x;
    int t   = threadIdx.x;           // 0..63
    int ow = bin % OW;
    int oh = (bin / OW) % OH;
    int n  = bin / QD;

    __shared__ int s_offs[MAX_CNT];  // featT element offsets, pre-multiplied by C_DIM

    // block-uniform bound math (identical in all threads)
    float img_h = decode_dim(img_h_p);
    float img_w = decode_dim(img_w_p);
    float sh = __fdiv_rn((float)FH, img_h);
    float sw = __fdiv_rn((float)FW, img_w);

    const float* r = rois + n * 5;
    int bidx = (int)r[0];
    int x1 = max((int)floorf(__fmul_rn(r[1], sw)), 0);
    int y1 = max((int)floorf(__fmul_rn(r[2], sh)), 0);
    int x2 = min((int)floorf(__fmul_rn(r[3], sw)), FW);
    int y2 = min((int)floorf(__fmul_rn(r[4], sh)), FH);

    float bh = __fdiv_rn((float)max(y2 - y1, 1), (float)OH);
    float bw = __fdiv_rn((float)max(x2 - x1, 1), (float)OW);
    float y1f = (float)y1, x1f = (float)x1;
    // mul then add, each correctly rounded (no FMA contraction) — matches jnp
    int ys = (int)floorf(__fadd_rn(y1f, __fmul_rn((float)oh,       bh)));
    int ye = (int)floorf(__fadd_rn(y1f, __fmul_rn((float)(oh + 1), bh)));
    int xs = (int)floorf(__fadd_rn(x1f, __fmul_rn((float)ow,       bw)));
    int xe = (int)floorf(__fadd_rn(x1f, __fmul_rn((float)(ow + 1), bw)));
    ys = min(max(ys, 0), FH - 1);
    ye = min(max(ye, 0), FH);
    xs = min(max(xs, 0), FW - 1);
    xe = min(max(xe, 0), FW);

    int rows = ye - ys;
    int cols = xe - xs;
    int count = (rows > 0 && cols > 0) ? rows * cols : 0;

    if (t < count) {
        int yy = ys + t / cols;
        int xx = xs + t % cols;
        s_offs[t] = (yy * FW + xx) * C_DIM;
    }
    __syncthreads();

    const float* base = g_featT + (size_t)bidx * (NPIX * C_DIM) + (t << 2);

    float4 m = make_float4(-INFINITY, -INFINITY, -INFINITY, -INFINITY);
    int i = 0;
    for (; i + 4 <= count; i += 4) {
        float4 a0 = *reinterpret_cast<const float4*>(base + s_offs[i + 0]);
        float4 a1 = *reinterpret_cast<const float4*>(base + s_offs[i + 1]);
        float4 a2 = *reinterpret_cast<const float4*>(base + s_offs[i + 2]);
        float4 a3 = *reinterpret_cast<const float4*>(base + s_offs[i + 3]);
        m = f4max(m, f4max(f4max(a0, a1), f4max(a2, a3)));
    }
    for (; i < count; ++i) {
        m = f4max(m, *reinterpret_cast<const float4*>(base + s_offs[i]));
    }
    if (count == 0) m = make_float4(0.f, 0.f, 0.f, 0.f);

    *reinterpret_cast<float4*>(g_outT + (size_t)bin * C_DIM + (t << 2)) = m;
}

// ---- K3: g_outT [n][q][c] -> out [n][c][q]; block per (n, channel-half) ----
__global__ void __launch_bounds__(256)
transpose_out(float* __restrict__ out) {
    __shared__ __align__(16) float s[128 * QD];   // [c_local][q], stride 49
    int n = blockIdx.x;
    int h = blockIdx.y;
    int tid = threadIdx.x;

    const float* src = g_outT + (size_t)n * (QD * C_DIM) + h * 128;
    for (int idx = tid; idx < QD * 128; idx += 256) {
        int q  = idx >> 7;
        int cl = idx & 127;
        s[cl * QD + q] = src[(size_t)q * C_DIM + cl];   // gmem coalesced
    }
    __syncthreads();

    float4* dst = reinterpret_cast<float4*>(
        out + (size_t)n * (C_DIM * QD) + (size_t)h * 128 * QD);
    const float4* ss = reinterpret_cast<const float4*>(s);
    for (int idx = tid; idx < (128 * QD) / 4; idx += 256) {
        dst[idx] = ss[idx];
    }
}

extern "C" void kernel_launch(void* const* d_in, const int* in_sizes, int n_in,
                              void* d_out, int out_size) {
    const float* feat = (const float*)d_in[0];
    const float* rois = (const float*)d_in[1];
    const void*  imh  = d_in[2];
    const void*  imw  = d_in[3];
    float* out = (float*)d_out;

    int B = in_sizes[0] / (C_DIM * NPIX);
    int nrois = in_sizes[1] / 5;
    int nbins = nrois * QD;

    int ntiles = PXT * CT * B;                   // 1264 for B=2
    transpose_in<<<(ntiles + 3) / 4, 256>>>(feat, ntiles);

    roipool_main<<<nbins, 64>>>(rois, imh, imw);

    dim3 og(nrois, 2);
    transpose_out<<<og, 256>>>(out);
}